// round 10
// baseline (speedup 1.0000x reference)
#include <cuda_runtime.h>
#include <cuda_bf16.h>
#include <stdint.h>

#define T 4096
#define D 2048
#define E 8

#define DATA  ((size_t)E * T * D)       // 64M floats (256 MB)
#define NTAG  (E * T)
#define SPLIT 1152                      // rows >= SPLIT zeroed by memset; [load_e,SPLIT) by tail blocks

// ---------------- scratch ----------------
__device__ int   g_top_e[T * 2];   // per token: top-2 expert ids
__device__ float g_top_g[T * 2];   // per token: top-2 gate values
__device__ int   g_tok_row[T * 2]; // per token slot: destination row in (E*T)
__device__ int   g_loads[E];
__device__ int   g_flag[T];        // 1 = near-tie at 2nd/3rd logit -> fp64 recompute

// ---------------- kernel 1: fp32 logits + softmax + top2 + tie flag ----------------
// 512 blocks x 256 threads; one token per warp. Wg^T staged in 2 chunks of 1024 d.
__global__ void __launch_bounds__(256) k_logits_f32(const float* __restrict__ x,
                                                    const float* __restrict__ Wg) {
    __shared__ float sW[8][1028];
    const int tid  = threadIdx.x;
    const int warp = tid >> 5;
    const int lane = tid & 31;
    const int t = blockIdx.x * 8 + warp;   // 0..4095

    float a[E];
#pragma unroll
    for (int e = 0; e < E; e++) a[e] = 0.f;

    for (int c = 0; c < 2; c++) {
        __syncthreads();
        const float4* wg4 = (const float4*)(Wg + (size_t)c * 1024 * 8);
        for (int j = tid; j < 2048; j += 256) {
            float4 v = wg4[j];
            int d  = j >> 1;
            int e0 = (j & 1) * 4;
            sW[e0 + 0][d] = v.x; sW[e0 + 1][d] = v.y;
            sW[e0 + 2][d] = v.z; sW[e0 + 3][d] = v.w;
        }
        __syncthreads();

        const float4* xr = (const float4*)(x + (size_t)t * D + c * 1024);
#pragma unroll
        for (int i = 0; i < 8; i++) {
            const int d4 = i * 32 + lane;
            float4 xv = xr[d4];
#pragma unroll
            for (int e = 0; e < E; e++) {
                float4 wv = *(const float4*)&sW[e][d4 * 4];
                a[e] += xv.x * wv.x + xv.y * wv.y + xv.z * wv.z + xv.w * wv.w;
            }
        }
    }

#pragma unroll
    for (int e = 0; e < E; e++) {
#pragma unroll
        for (int off = 16; off > 0; off >>= 1)
            a[e] += __shfl_down_sync(0xffffffffu, a[e], off);
    }

    if (lane == 0) {
        float lg[E];
#pragma unroll
        for (int e = 0; e < E; e++) lg[e] = a[e];

        float mx = lg[0];
#pragma unroll
        for (int e = 1; e < E; e++) mx = fmaxf(mx, lg[e]);
        float ex[E], sum = 0.f;
#pragma unroll
        for (int e = 0; e < E; e++) { ex[e] = __expf(lg[e] - mx); sum += ex[e]; }
        float inv = 1.0f / sum;

        int b0 = 0;
#pragma unroll
        for (int e = 1; e < E; e++) if (lg[e] > lg[b0]) b0 = e;
        int b1 = -1;
#pragma unroll
        for (int e = 0; e < E; e++) {
            if (e == b0) continue;
            if (b1 < 0 || lg[e] > lg[b1]) b1 = e;
        }
        float v3 = -1e30f;
#pragma unroll
        for (int e = 0; e < E; e++)
            if (e != b0 && e != b1) v3 = fmaxf(v3, lg[e]);

        g_top_e[t * 2 + 0] = b0;
        g_top_e[t * 2 + 1] = b1;
        g_top_g[t * 2 + 0] = ex[b0] * inv;
        g_top_g[t * 2 + 1] = ex[b1] * inv;
        g_flag[t] = (lg[b1] - v3 < 1e-3f) ? 1 : 0;
    }
}

// ---------------- kernel 2: fp64 fixup for flagged tokens + compaction + loads ----------------
__global__ void k_route(const float* __restrict__ x, const float* __restrict__ Wg,
                        float* __restrict__ out) {
    const int NT = 512, TPB = T / NT;  // 8
    const int tid = threadIdx.x;
    const int lane = tid & 31, wid = tid >> 5;  // 16 warps
    __shared__ int wsum[16];
    __shared__ int s_list[T];
    __shared__ int s_n;
    __shared__ double sred[16][8];
    __shared__ double slog[8];

    if (tid == 0) s_n = 0;
    __syncthreads();
    for (int t = tid; t < T; t += NT)
        if (g_flag[t]) { int k = atomicAdd(&s_n, 1); s_list[k] = t; }
    __syncthreads();

    for (int k = 0; k < s_n; k++) {
        const int t = s_list[k];
        double acc[E];
#pragma unroll
        for (int e = 0; e < E; e++) acc[e] = 0.0;
#pragma unroll
        for (int kk = 0; kk < 4; kk++) {
            const int d = tid + kk * NT;
            const double xv = (double)x[(size_t)t * D + d];
            const float4* w4 = (const float4*)(Wg + (size_t)d * 8);
            float4 wa = w4[0], wb = w4[1];
            acc[0] += xv * (double)wa.x; acc[1] += xv * (double)wa.y;
            acc[2] += xv * (double)wa.z; acc[3] += xv * (double)wa.w;
            acc[4] += xv * (double)wb.x; acc[5] += xv * (double)wb.y;
            acc[6] += xv * (double)wb.z; acc[7] += xv * (double)wb.w;
        }
#pragma unroll
        for (int e = 0; e < E; e++) {
#pragma unroll
            for (int off = 16; off > 0; off >>= 1)
                acc[e] += __shfl_down_sync(0xffffffffu, acc[e], off);
        }
        if (lane == 0) {
#pragma unroll
            for (int e = 0; e < E; e++) sred[wid][e] = acc[e];
        }
        __syncthreads();
        if (tid < E) {
            double s = 0.0;
#pragma unroll
            for (int w = 0; w < 16; w++) s += sred[w][tid];
            slog[tid] = s;
        }
        __syncthreads();
        if (tid == 0) {
            float lg[E];
#pragma unroll
            for (int e = 0; e < E; e++) lg[e] = (float)slog[e];
            float mx = lg[0];
#pragma unroll
            for (int e = 1; e < E; e++) mx = fmaxf(mx, lg[e]);
            float ex[E], sum = 0.f;
#pragma unroll
            for (int e = 0; e < E; e++) { ex[e] = __expf(lg[e] - mx); sum += ex[e]; }
            float inv = 1.0f / sum;
            int b0 = 0;
#pragma unroll
            for (int e = 1; e < E; e++) if (lg[e] > lg[b0]) b0 = e;
            int b1 = -1;
#pragma unroll
            for (int e = 0; e < E; e++) {
                if (e == b0) continue;
                if (b1 < 0 || lg[e] > lg[b1]) b1 = e;
            }
            g_top_e[t * 2 + 0] = b0;
            g_top_e[t * 2 + 1] = b1;
            g_top_g[t * 2 + 0] = ex[b0] * inv;
            g_top_g[t * 2 + 1] = ex[b1] * inv;
        }
        __syncthreads();
    }

    // ---- ordered per-expert compaction ----
    int e0[TPB], e1[TPB];
    const int t0 = tid * TPB;
#pragma unroll
    for (int j = 0; j < TPB; j++) {
        e0[j] = g_top_e[(t0 + j) * 2 + 0];
        e1[j] = g_top_e[(t0 + j) * 2 + 1];
    }
    __syncthreads();

    for (int e = 0; e < E; e++) {
        int cnt = 0;
#pragma unroll
        for (int j = 0; j < TPB; j++) cnt += (e0[j] == e) + (e1[j] == e);

        int incl = cnt;
#pragma unroll
        for (int off = 1; off < 32; off <<= 1) {
            int v = __shfl_up_sync(0xffffffffu, incl, off);
            if (lane >= off) incl += v;
        }
        if (lane == 31) wsum[wid] = incl;
        __syncthreads();
        if (tid < 32) {
            int v = (tid < 16) ? wsum[tid] : 0;
#pragma unroll
            for (int off = 1; off < 16; off <<= 1) {
                int u = __shfl_up_sync(0xffffffffu, v, off);
                if (lane >= off) v += u;
            }
            if (tid < 16) wsum[tid] = v;
        }
        __syncthreads();

        int wbase = wid ? wsum[wid - 1] : 0;
        int p = wbase + incl - cnt;
#pragma unroll
        for (int j = 0; j < TPB; j++) {
            if (e0[j] == e) {
                g_tok_row[(t0 + j) * 2 + 0] = e * T + p; p++;
            } else if (e1[j] == e) {
                g_tok_row[(t0 + j) * 2 + 1] = e * T + p; p++;
            }
        }
        if (tid == 0) {
            g_loads[e] = wsum[15];
            out[DATA + NTAG + e] = (float)wsum[15];   // loads output
        }
        __syncthreads();  // before wsum reuse
    }
}

// ---------------- kernel 3: scatter rows+tags, tag tails, gap-row zeroing ----------------
// blocks [0,T): token t -> 2 data rows + 2 occupied tags
// blocks [T, T+64): expert e=(u)/8, slice s=u%8:
//    tags   rows [load_e, T)     -> -1
//    data   rows [load_e, SPLIT) -> 0   (gap between scatter coverage and memset region)
__global__ void k_scatter(const float* __restrict__ x, float* __restrict__ out) {
    const int bid = blockIdx.x;
    const int i = threadIdx.x;

    if (bid >= T) {
        const int u = bid - T;
        const int e = u >> 3;
        const int s = u & 7;
        const int le = g_loads[e];
        for (int r = le + s * 256 + i; r < T; r += 8 * 256)
            out[DATA + e * T + r] = -1.0f;
        const float4 z = make_float4(0.f, 0.f, 0.f, 0.f);
        for (int r = le + s; r < SPLIT; r += 8) {
            float4* o = (float4*)(out + ((size_t)e * T + r) * D);
            o[i] = z;
            o[i + 256] = z;
        }
        return;
    }

    const int t = bid;
    const int r0 = g_tok_row[t * 2 + 0];
    const int r1 = g_tok_row[t * 2 + 1];
    const float s0 = g_top_g[t * 2 + 0];
    const float s1 = g_top_g[t * 2 + 1];

    const float4* xr = (const float4*)(x + (size_t)t * D);
    float4* o0 = (float4*)(out + (size_t)r0 * D);
    float4* o1 = (float4*)(out + (size_t)r1 * D);

    float4 a = xr[i], b = xr[i + 256];
    o0[i]       = make_float4(a.x * s0, a.y * s0, a.z * s0, a.w * s0);
    o0[i + 256] = make_float4(b.x * s0, b.y * s0, b.z * s0, b.w * s0);
    o1[i]       = make_float4(a.x * s1, a.y * s1, a.z * s1, a.w * s1);
    o1[i + 256] = make_float4(b.x * s1, b.y * s1, b.z * s1, b.w * s1);

    if (i == 0) out[DATA + r0] = (float)t;
    if (i == 1) out[DATA + r1] = (float)t;
}

// ---------------- launch ----------------
extern "C" void kernel_launch(void* const* d_in, const int* in_sizes, int n_in,
                              void* d_out, int out_size) {
    const float* x  = (const float*)d_in[0];
    const float* Wg = (const float*)d_in[1];
    float* out = (float*)d_out;

    // zero only rows [SPLIT, T) of each expert (scatter + tail blocks cover the rest)
    for (int e = 0; e < E; e++)
        cudaMemsetAsync(out + ((size_t)e * T + SPLIT) * D, 0,
                        (size_t)(T - SPLIT) * D * sizeof(float));

    k_logits_f32<<<512, 256>>>(x, Wg);
    k_route<<<1, 512>>>(x, Wg, out);
    k_scatter<<<T + 64, 256>>>(x, out);
}

// round 11
// speedup vs baseline: 1.1019x; 1.1019x over previous
#include <cuda_runtime.h>
#include <cuda_bf16.h>
#include <stdint.h>

#define T 4096
#define D 2048
#define E 8

#define DATA  ((size_t)E * T * D)       // 64M floats (256 MB)
#define NTAG  (E * T)
#define NZB   2048                      // zero blocks in fill kernel (8 experts x 256 slices)
#define FGRID (NZB + T)                 // 6144

// ---------------- scratch ----------------
__device__ int   g_top_e[T * 2];   // per token: top-2 expert ids
__device__ float g_top_g[T * 2];   // per token: top-2 gate values
__device__ int   g_tok_row[T * 2]; // per token slot: destination row in (E*T)
__device__ int   g_loads[E];
__device__ int   g_flag[T];        // 1 = near-tie at 2nd/3rd logit -> fp64 recompute

// ---------------- kernel 1: fp32 logits, 4 tokens/warp (LDS amortized 4x) ----------------
// 128 blocks x 256 threads (8 warps); warp handles tokens [gw*4, gw*4+4).
__global__ void __launch_bounds__(256) k_logits_f32(const float* __restrict__ x,
                                                    const float* __restrict__ Wg) {
    __shared__ float sW[8][1028];
    const int tid  = threadIdx.x;
    const int warp = tid >> 5;
    const int lane = tid & 31;
    const int tb = (blockIdx.x * 8 + warp) * 4;   // first of 4 tokens

    float a0[E], a1[E], a2[E], a3[E];
#pragma unroll
    for (int e = 0; e < E; e++) { a0[e] = 0.f; a1[e] = 0.f; a2[e] = 0.f; a3[e] = 0.f; }

    for (int c = 0; c < 2; c++) {
        __syncthreads();
        const float4* wg4 = (const float4*)(Wg + (size_t)c * 1024 * 8);
        for (int j = tid; j < 2048; j += 256) {
            float4 v = wg4[j];
            int d  = j >> 1;
            int eb = (j & 1) * 4;
            sW[eb + 0][d] = v.x; sW[eb + 1][d] = v.y;
            sW[eb + 2][d] = v.z; sW[eb + 3][d] = v.w;
        }
        __syncthreads();

        const float4* x0 = (const float4*)(x + (size_t)(tb + 0) * D + c * 1024);
        const float4* x1 = (const float4*)(x + (size_t)(tb + 1) * D + c * 1024);
        const float4* x2 = (const float4*)(x + (size_t)(tb + 2) * D + c * 1024);
        const float4* x3 = (const float4*)(x + (size_t)(tb + 3) * D + c * 1024);
#pragma unroll
        for (int i = 0; i < 8; i++) {
            const int d4 = i * 32 + lane;
            float4 v0 = x0[d4], v1 = x1[d4], v2 = x2[d4], v3 = x3[d4];
#pragma unroll
            for (int e = 0; e < E; e++) {
                float4 wv = *(const float4*)&sW[e][d4 * 4];
                a0[e] += v0.x * wv.x + v0.y * wv.y + v0.z * wv.z + v0.w * wv.w;
                a1[e] += v1.x * wv.x + v1.y * wv.y + v1.z * wv.z + v1.w * wv.w;
                a2[e] += v2.x * wv.x + v2.y * wv.y + v2.z * wv.z + v2.w * wv.w;
                a3[e] += v3.x * wv.x + v3.y * wv.y + v3.z * wv.z + v3.w * wv.w;
            }
        }
    }

#pragma unroll
    for (int e = 0; e < E; e++) {
#pragma unroll
        for (int off = 16; off > 0; off >>= 1) {
            a0[e] += __shfl_down_sync(0xffffffffu, a0[e], off);
            a1[e] += __shfl_down_sync(0xffffffffu, a1[e], off);
            a2[e] += __shfl_down_sync(0xffffffffu, a2[e], off);
            a3[e] += __shfl_down_sync(0xffffffffu, a3[e], off);
        }
    }

    if (lane == 0) {
#pragma unroll
        for (int k = 0; k < 4; k++) {
            const int t = tb + k;
            float lg[E];
#pragma unroll
            for (int e = 0; e < E; e++)
                lg[e] = (k == 0) ? a0[e] : (k == 1) ? a1[e] : (k == 2) ? a2[e] : a3[e];

            float mx = lg[0];
#pragma unroll
            for (int e = 1; e < E; e++) mx = fmaxf(mx, lg[e]);
            float ex[E], sum = 0.f;
#pragma unroll
            for (int e = 0; e < E; e++) { ex[e] = __expf(lg[e] - mx); sum += ex[e]; }
            float inv = 1.0f / sum;

            int b0 = 0;
#pragma unroll
            for (int e = 1; e < E; e++) if (lg[e] > lg[b0]) b0 = e;
            int b1 = -1;
#pragma unroll
            for (int e = 0; e < E; e++) {
                if (e == b0) continue;
                if (b1 < 0 || lg[e] > lg[b1]) b1 = e;
            }
            float v3 = -1e30f;
#pragma unroll
            for (int e = 0; e < E; e++)
                if (e != b0 && e != b1) v3 = fmaxf(v3, lg[e]);

            g_top_e[t * 2 + 0] = b0;
            g_top_e[t * 2 + 1] = b1;
            g_top_g[t * 2 + 0] = ex[b0] * inv;
            g_top_g[t * 2 + 1] = ex[b1] * inv;
            g_flag[t] = (lg[b1] - v3 < 1e-3f) ? 1 : 0;
        }
    }
}

// ---------------- kernel 2: fp64 fixup for flagged tokens + compaction + loads ----------------
__global__ void k_route(const float* __restrict__ x, const float* __restrict__ Wg,
                        float* __restrict__ out) {
    const int NT = 512, TPB = T / NT;  // 8
    const int tid = threadIdx.x;
    const int lane = tid & 31, wid = tid >> 5;  // 16 warps
    __shared__ int wsum[16];
    __shared__ int s_list[T];
    __shared__ int s_n;
    __shared__ double sred[16][8];
    __shared__ double slog[8];

    if (tid == 0) s_n = 0;
    __syncthreads();
    for (int t = tid; t < T; t += NT)
        if (g_flag[t]) { int k = atomicAdd(&s_n, 1); s_list[k] = t; }
    __syncthreads();

    for (int k = 0; k < s_n; k++) {
        const int t = s_list[k];
        double acc[E];
#pragma unroll
        for (int e = 0; e < E; e++) acc[e] = 0.0;
#pragma unroll
        for (int kk = 0; kk < 4; kk++) {
            const int d = tid + kk * NT;
            const double xv = (double)x[(size_t)t * D + d];
            const float4* w4 = (const float4*)(Wg + (size_t)d * 8);
            float4 wa = w4[0], wb = w4[1];
            acc[0] += xv * (double)wa.x; acc[1] += xv * (double)wa.y;
            acc[2] += xv * (double)wa.z; acc[3] += xv * (double)wa.w;
            acc[4] += xv * (double)wb.x; acc[5] += xv * (double)wb.y;
            acc[6] += xv * (double)wb.z; acc[7] += xv * (double)wb.w;
        }
#pragma unroll
        for (int e = 0; e < E; e++) {
#pragma unroll
            for (int off = 16; off > 0; off >>= 1)
                acc[e] += __shfl_down_sync(0xffffffffu, acc[e], off);
        }
        if (lane == 0) {
#pragma unroll
            for (int e = 0; e < E; e++) sred[wid][e] = acc[e];
        }
        __syncthreads();
        if (tid < E) {
            double s = 0.0;
#pragma unroll
            for (int w = 0; w < 16; w++) s += sred[w][tid];
            slog[tid] = s;
        }
        __syncthreads();
        if (tid == 0) {
            float lg[E];
#pragma unroll
            for (int e = 0; e < E; e++) lg[e] = (float)slog[e];
            float mx = lg[0];
#pragma unroll
            for (int e = 1; e < E; e++) mx = fmaxf(mx, lg[e]);
            float ex[E], sum = 0.f;
#pragma unroll
            for (int e = 0; e < E; e++) { ex[e] = __expf(lg[e] - mx); sum += ex[e]; }
            float inv = 1.0f / sum;
            int b0 = 0;
#pragma unroll
            for (int e = 1; e < E; e++) if (lg[e] > lg[b0]) b0 = e;
            int b1 = -1;
#pragma unroll
            for (int e = 0; e < E; e++) {
                if (e == b0) continue;
                if (b1 < 0 || lg[e] > lg[b1]) b1 = e;
            }
            g_top_e[t * 2 + 0] = b0;
            g_top_e[t * 2 + 1] = b1;
            g_top_g[t * 2 + 0] = ex[b0] * inv;
            g_top_g[t * 2 + 1] = ex[b1] * inv;
        }
        __syncthreads();
    }

    // ---- ordered per-expert compaction ----
    int e0[TPB], e1[TPB];
    const int t0 = tid * TPB;
#pragma unroll
    for (int j = 0; j < TPB; j++) {
        e0[j] = g_top_e[(t0 + j) * 2 + 0];
        e1[j] = g_top_e[(t0 + j) * 2 + 1];
    }
    __syncthreads();

    for (int e = 0; e < E; e++) {
        int cnt = 0;
#pragma unroll
        for (int j = 0; j < TPB; j++) cnt += (e0[j] == e) + (e1[j] == e);

        int incl = cnt;
#pragma unroll
        for (int off = 1; off < 32; off <<= 1) {
            int v = __shfl_up_sync(0xffffffffu, incl, off);
            if (lane >= off) incl += v;
        }
        if (lane == 31) wsum[wid] = incl;
        __syncthreads();
        if (tid < 32) {
            int v = (tid < 16) ? wsum[tid] : 0;
#pragma unroll
            for (int off = 1; off < 16; off <<= 1) {
                int u = __shfl_up_sync(0xffffffffu, v, off);
                if (lane >= off) v += u;
            }
            if (tid < 16) wsum[tid] = v;
        }
        __syncthreads();

        int wbase = wid ? wsum[wid - 1] : 0;
        int p = wbase + incl - cnt;
#pragma unroll
        for (int j = 0; j < TPB; j++) {
            if (e0[j] == e) {
                g_tok_row[(t0 + j) * 2 + 0] = e * T + p; p++;
            } else if (e1[j] == e) {
                g_tok_row[(t0 + j) * 2 + 1] = e * T + p; p++;
            }
        }
        if (tid == 0) {
            g_loads[e] = wsum[15];
            out[DATA + NTAG + e] = (float)wsum[15];   // loads output
        }
        __syncthreads();  // before wsum reuse
    }
}

// ---------------- kernel 3: fill — zero blocks + scatter blocks in one launch ----------------
// bid % 3 == 0 -> zero unit zu = bid/3 (0..2047): expert e = zu&7, slice s = zu>>3;
//                 rows r = load_e + s, step 256 while r < T: data row -> 0, tag -> -1
// else         -> scatter token t = bid - bid/3 - 1 (0..4095): 2 data rows + 2 tags
__global__ void k_fill(const float* __restrict__ x, float* __restrict__ out) {
    const int bid = blockIdx.x;
    const int i = threadIdx.x;

    if (bid % 3 == 0) {
        const int zu = bid / 3;
        const int e = zu & 7;
        const int s = zu >> 3;           // 0..255
        const int le = g_loads[e];
        const float4 z = make_float4(0.f, 0.f, 0.f, 0.f);
        for (int r = le + s; r < T; r += 256) {
            float4* o = (float4*)(out + ((size_t)e * T + r) * D);
            o[i] = z;
            o[i + 256] = z;
            if (i == 0) out[DATA + e * T + r] = -1.0f;
        }
        return;
    }

    const int t = bid - bid / 3 - 1;
    const int r0 = g_tok_row[t * 2 + 0];
    const int r1 = g_tok_row[t * 2 + 1];
    const float s0 = g_top_g[t * 2 + 0];
    const float s1 = g_top_g[t * 2 + 1];

    const float4* xr = (const float4*)(x + (size_t)t * D);
    float4* o0 = (float4*)(out + (size_t)r0 * D);
    float4* o1 = (float4*)(out + (size_t)r1 * D);

    float4 a = xr[i], b = xr[i + 256];
    o0[i]       = make_float4(a.x * s0, a.y * s0, a.z * s0, a.w * s0);
    o0[i + 256] = make_float4(b.x * s0, b.y * s0, b.z * s0, b.w * s0);
    o1[i]       = make_float4(a.x * s1, a.y * s1, a.z * s1, a.w * s1);
    o1[i + 256] = make_float4(b.x * s1, b.y * s1, b.z * s1, b.w * s1);

    if (i == 0) out[DATA + r0] = (float)t;
    if (i == 1) out[DATA + r1] = (float)t;
}

// ---------------- launch ----------------
extern "C" void kernel_launch(void* const* d_in, const int* in_sizes, int n_in,
                              void* d_out, int out_size) {
    const float* x  = (const float*)d_in[0];
    const float* Wg = (const float*)d_in[1];
    float* out = (float*)d_out;

    k_logits_f32<<<128, 256>>>(x, Wg);
    k_route<<<1, 512>>>(x, Wg, out);
    k_fill<<<FGRID, 256>>>(x, out);
}